// round 5
// baseline (speedup 1.0000x reference)
#include <cuda_runtime.h>
#include <math.h>

// Problem constants
#define BB 8
#define CC 128
#define HWM 4096          // H*W = 64*64
#define TN 64             // K/V tile (columns of n)
#define NTHREADS 256

// Folded classifier-head weights (BN folded into w1), built by prep_kernel.
__device__ float g_At[3 * CC * CC];   // At[c][o] = w1[o][c] * inv[o], c in [0,384), o in [0,128)
__device__ float g_dv[CC];            // dv[o] = b1[o]*inv[o] + beta[o] - mean[o]*inv[o]

__global__ void prep_kernel(const float* __restrict__ w1, const float* __restrict__ b1,
                            const float* __restrict__ gamma, const float* __restrict__ beta,
                            const float* __restrict__ rmean, const float* __restrict__ rvar)
{
    int i = blockIdx.x * blockDim.x + threadIdx.x;
    if (i < 3 * CC * CC) {
        int c = i / CC;
        int o = i % CC;
        float inv = gamma[o] * rsqrtf(rvar[o] + 1e-5f);
        g_At[c * CC + o] = w1[o * (3 * CC) + c] * inv;
    }
    if (i < CC) {
        float inv = gamma[i] * rsqrtf(rvar[i] + 1e-5f);
        g_dv[i] = b1[i] * inv + beta[i] - rmean[i] * inv;
    }
}

// Fused dual-attention + cls head.
// Grid: (HWM/32, BB). Block: 256 threads = 16x16 (tx = col-group, ty = row-group).
// Per CTA: 32 query positions m0..m0+31 of batch b.
//   Logical query rows r in [0,64): r<32 -> Q = ref (cross-attn / feats0),
//                                   r>=32 -> Q = cur (self-attn / feats1).
// Streams K=V=cur in 64-wide tiles with online softmax; feats accumulate in regs.
// Epilogue: x = [feats0; feats1; cur] (384), y = At^T... y_o = sum_c At[c][o]*x[c] + dv[o],
// leaky(0.01), pred = sum_o w2[o]*leaky(y_o) + b2.
//
// Shared memory layout (dynamic, 99328 bytes):
//   Qs : [128][64]  floats at offset 0      (8192 floats)  queries, k-major, pre-scaled
//   Ks : [128][64]  floats at offset 8192   (8192 floats)  K tile, k-major
//   KsT: [64][132]  floats at offset 16384  (8448 floats)  K tile transposed (j-major)
//   Ps : [64][68]   floats  -- ALIASES Ks (used after S-phase reads of Ks complete)
// Epilogue reuses the whole region:
//   Xs : [384][36] at offset 0, Ys : [128][33] at offset 13824.

__global__ void __launch_bounds__(NTHREADS, 2)
fused_attn_kernel(const float* __restrict__ reff, const float* __restrict__ curf,
                  const float* __restrict__ w2, const float* __restrict__ b2,
                  float* __restrict__ out)
{
    extern __shared__ float sm[];
    float* Qs  = sm;            // 8192
    float* Ks  = sm + 8192;     // 8192
    float* KsT = sm + 16384;    // 8448
    float* Ps  = Ks;            // alias (4352 <= 8192)

    const int b   = blockIdx.y;
    const int m0  = blockIdx.x * 32;
    const int tid = threadIdx.x;
    const int tx  = tid & 15;
    const int ty  = tid >> 4;

    const float* __restrict__ curb = curf + (size_t)b * CC * HWM;
    const float* __restrict__ refb = reff + (size_t)b * CC * HWM;

    const float scale = 0.08838834764831845f;  // 1/sqrt(128)

    // ---- Load Q tile (scaled). Rows 0..31 = ref, 32..63 = cur. ----
    for (int i = tid; i < CC * 64; i += NTHREADS) {
        int k = i >> 6;
        int r = i & 63;
        float v = (r < 32) ? refb[k * HWM + m0 + r]
                           : curb[k * HWM + m0 + (r - 32)];
        Qs[k * 64 + r] = v * scale;
    }

    // Accumulators: thread owns channels {tx*4..tx*4+3} U {64+tx*4..64+tx*4+3}
    // and logical rows {ty*4..ty*4+3}.
    float acc[8][4];
    #pragma unroll
    for (int ci = 0; ci < 8; ci++)
        #pragma unroll
        for (int ri = 0; ri < 4; ri++) acc[ci][ri] = 0.0f;

    float m_i[4], l_i[4];
    #pragma unroll
    for (int ri = 0; ri < 4; ri++) { m_i[ri] = -INFINITY; l_i[ri] = 0.0f; }

    // ---- Main loop over K/V tiles ----
    for (int nt = 0; nt < HWM / TN; nt++) {
        const int n0 = nt * TN;

        __syncthreads();  // previous PV reads of Ps/KsT done before overwrite
        for (int i = tid; i < CC * TN; i += NTHREADS) {
            int k = i >> 6;
            int j = i & 63;
            float v = curb[k * HWM + n0 + j];
            Ks[k * 64 + j]   = v;
            KsT[j * 132 + k] = v;
        }
        __syncthreads();

        // S = Q^T K  (64 x 64 tile, 4x4 per thread)
        float s[4][4];
        #pragma unroll
        for (int ri = 0; ri < 4; ri++)
            #pragma unroll
            for (int ci = 0; ci < 4; ci++) s[ri][ci] = 0.0f;

        #pragma unroll 4
        for (int k = 0; k < CC; k++) {
            float4 q  = *(const float4*)(Qs + k * 64 + ty * 4);
            float4 kv = *(const float4*)(Ks + k * 64 + tx * 4);
            float qa[4] = {q.x, q.y, q.z, q.w};
            float kb[4] = {kv.x, kv.y, kv.z, kv.w};
            #pragma unroll
            for (int ri = 0; ri < 4; ri++)
                #pragma unroll
                for (int ci = 0; ci < 4; ci++)
                    s[ri][ci] += qa[ri] * kb[ci];
        }

        // Online softmax (row stats across the 16 tx lanes; xor<=8 stays in half-warp)
        float rmax[4], rsum[4], alpha[4];
        #pragma unroll
        for (int ri = 0; ri < 4; ri++) {
            float mx = s[ri][0];
            mx = fmaxf(mx, s[ri][1]);
            mx = fmaxf(mx, s[ri][2]);
            mx = fmaxf(mx, s[ri][3]);
            rmax[ri] = mx;
        }
        #pragma unroll
        for (int off = 1; off < 16; off <<= 1)
            #pragma unroll
            for (int ri = 0; ri < 4; ri++)
                rmax[ri] = fmaxf(rmax[ri], __shfl_xor_sync(0xffffffffu, rmax[ri], off));

        #pragma unroll
        for (int ri = 0; ri < 4; ri++) {
            float mn = fmaxf(m_i[ri], rmax[ri]);
            alpha[ri] = __expf(m_i[ri] - mn);   // exp(-inf)=0 on first tile
            m_i[ri] = mn;
            rsum[ri] = 0.0f;
        }
        #pragma unroll
        for (int ri = 0; ri < 4; ri++)
            #pragma unroll
            for (int ci = 0; ci < 4; ci++) {
                float p = __expf(s[ri][ci] - m_i[ri]);
                s[ri][ci] = p;
                rsum[ri] += p;
            }
        #pragma unroll
        for (int off = 1; off < 16; off <<= 1)
            #pragma unroll
            for (int ri = 0; ri < 4; ri++)
                rsum[ri] += __shfl_xor_sync(0xffffffffu, rsum[ri], off);

        #pragma unroll
        for (int ri = 0; ri < 4; ri++)
            l_i[ri] = l_i[ri] * alpha[ri] + rsum[ri];

        #pragma unroll
        for (int ci = 0; ci < 8; ci++)
            #pragma unroll
            for (int ri = 0; ri < 4; ri++)
                acc[ci][ri] *= alpha[ri];

        __syncthreads();  // all S-phase reads of Ks done (Ps aliases Ks)

        // Stage P (unnormalized) to smem, j-major: Ps[j][r]
        #pragma unroll
        for (int ci = 0; ci < 4; ci++) {
            int j = tx * 4 + ci;
            *(float4*)(Ps + j * 68 + ty * 4) =
                make_float4(s[0][ci], s[1][ci], s[2][ci], s[3][ci]);
        }
        __syncthreads();

        // feats += P * V  (V = K tile, read via KsT)
        #pragma unroll 2
        for (int j = 0; j < TN; j++) {
            float4 p4 = *(const float4*)(Ps + j * 68 + ty * 4);
            float4 v0 = *(const float4*)(KsT + j * 132 + tx * 4);
            float4 v1 = *(const float4*)(KsT + j * 132 + 64 + tx * 4);
            float pr[4] = {p4.x, p4.y, p4.z, p4.w};
            float va[8] = {v0.x, v0.y, v0.z, v0.w, v1.x, v1.y, v1.z, v1.w};
            #pragma unroll
            for (int ci = 0; ci < 8; ci++)
                #pragma unroll
                for (int ri = 0; ri < 4; ri++)
                    acc[ci][ri] += va[ci] * pr[ri];
        }
    }
    __syncthreads();  // attention done; smem free for epilogue

    // ---- Epilogue: build X = [feats0; feats1; cur] in smem ----
    float* Xs = sm;            // [384][36]
    float* Ys = sm + 384 * 36; // [128][33]

    float rl[4];
    #pragma unroll
    for (int ri = 0; ri < 4; ri++) rl[ri] = 1.0f / l_i[ri];

    #pragma unroll
    for (int ci = 0; ci < 8; ci++) {
        int c = (ci < 4) ? (tx * 4 + ci) : (64 + tx * 4 + (ci - 4));
        #pragma unroll
        for (int ri = 0; ri < 4; ri++) {
            int r  = ty * 4 + ri;
            int a  = r >> 5;      // 0 = feats0 (ref-query), 1 = feats1 (cur-query)
            int ml = r & 31;
            Xs[(a * CC + c) * 36 + ml] = acc[ci][ri] * rl[ri];
        }
    }
    for (int i = tid; i < CC * 32; i += NTHREADS) {
        int c  = i >> 5;
        int ml = i & 31;
        Xs[(2 * CC + c) * 36 + ml] = curb[c * HWM + m0 + ml];
    }
    __syncthreads();

    // y[o][m] = sum_c At[c][o] * X[c][m] + dv[o]; then leaky, premultiply by w2[o]
    {
        int o    = tid & 127;
        int half = tid >> 7;     // 0/1 -> m-range halves
        float y[16];
        float dv = g_dv[o];
        #pragma unroll
        for (int q = 0; q < 16; q++) y[q] = dv;

        #pragma unroll 4
        for (int c = 0; c < 3 * CC; c++) {
            float a = g_At[c * CC + o];
            const float4* xp = (const float4*)(Xs + c * 36 + half * 16);
            float4 x0 = xp[0], x1 = xp[1], x2 = xp[2], x3 = xp[3];
            y[0]  += a * x0.x; y[1]  += a * x0.y; y[2]  += a * x0.z; y[3]  += a * x0.w;
            y[4]  += a * x1.x; y[5]  += a * x1.y; y[6]  += a * x1.z; y[7]  += a * x1.w;
            y[8]  += a * x2.x; y[9]  += a * x2.y; y[10] += a * x2.z; y[11] += a * x2.w;
            y[12] += a * x3.x; y[13] += a * x3.y; y[14] += a * x3.z; y[15] += a * x3.w;
        }
        float w2o = w2[o];
        #pragma unroll
        for (int q = 0; q < 16; q++) {
            float v = y[q];
            v = (v > 0.0f) ? v : 0.01f * v;
            Ys[o * 33 + half * 16 + q] = w2o * v;
        }
    }
    __syncthreads();

    if (tid < 32) {
        float ssum = b2[0];
        #pragma unroll 4
        for (int o = 0; o < CC; o++) ssum += Ys[o * 33 + tid];
        out[b * HWM + m0 + tid] = ssum;
    }
}

extern "C" void kernel_launch(void* const* d_in, const int* in_sizes, int n_in,
                              void* d_out, int out_size)
{
    const float* ref_feat = (const float*)d_in[0];
    const float* cur_feat = (const float*)d_in[1];
    const float* w1       = (const float*)d_in[2];
    const float* b1       = (const float*)d_in[3];
    const float* gamma    = (const float*)d_in[4];
    const float* beta     = (const float*)d_in[5];
    const float* rmean    = (const float*)d_in[6];
    const float* rvar     = (const float*)d_in[7];
    const float* w2       = (const float*)d_in[8];
    const float* b2       = (const float*)d_in[9];
    float* out            = (float*)d_out;

    // Fold BN into w1 (tiny).
    prep_kernel<<<(3 * CC * CC + 255) / 256, 256>>>(w1, b1, gamma, beta, rmean, rvar);

    const int smem_bytes = (8192 + 8192 + 64 * 132) * 4;  // 99328
    cudaFuncSetAttribute(fused_attn_kernel,
                         cudaFuncAttributeMaxDynamicSharedMemorySize, smem_bytes);

    dim3 grid(HWM / 32, BB);
    fused_attn_kernel<<<grid, NTHREADS, smem_bytes>>>(ref_feat, cur_feat, w2, b2, out);
}

// round 6
// speedup vs baseline: 2.7730x; 2.7730x over previous
#include <cuda_runtime.h>
#include <math.h>
#include <stdint.h>

#define BB 8
#define CC 128
#define HWM 4096          // H*W
#define TN 64             // K/V tile width
#define NTHREADS 256

// Folded classifier-head weights (BN folded into w1).
__device__ float g_At[3 * CC * CC];   // At[c][o] = w1[o][c] * inv[o]
__device__ float g_dv[CC];

__global__ void prep_kernel(const float* __restrict__ w1, const float* __restrict__ b1,
                            const float* __restrict__ gamma, const float* __restrict__ beta,
                            const float* __restrict__ rmean, const float* __restrict__ rvar)
{
    int i = blockIdx.x * blockDim.x + threadIdx.x;
    if (i < 3 * CC * CC) {
        int c = i / CC;
        int o = i % CC;
        float inv = gamma[o] * rsqrtf(rvar[o] + 1e-5f);
        g_At[c * CC + o] = w1[o * (3 * CC) + c] * inv;
    }
    if (i < CC) {
        float inv = gamma[i] * rsqrtf(rvar[i] + 1e-5f);
        g_dv[i] = b1[i] * inv + beta[i] - rmean[i] * inv;
    }
}

// ---------- PTX helpers ----------
__device__ __forceinline__ uint32_t smem_u32(const void* p) {
    return (uint32_t)__cvta_generic_to_shared(p);
}

__device__ __forceinline__ void ldsm4(uint32_t& r0, uint32_t& r1, uint32_t& r2, uint32_t& r3,
                                      uint32_t addr) {
    asm volatile("ldmatrix.sync.aligned.m8n8.x4.shared.b16 {%0,%1,%2,%3}, [%4];"
                 : "=r"(r0), "=r"(r1), "=r"(r2), "=r"(r3) : "r"(addr));
}

__device__ __forceinline__ void mma_tf32(float& d0, float& d1, float& d2, float& d3,
                                         uint32_t a0, uint32_t a1, uint32_t a2, uint32_t a3,
                                         uint32_t b0, uint32_t b1) {
    asm volatile("mma.sync.aligned.m16n8k8.row.col.f32.tf32.tf32.f32 "
                 "{%0,%1,%2,%3}, {%4,%5,%6,%7}, {%8,%9}, {%0,%1,%2,%3};"
                 : "+f"(d0), "+f"(d1), "+f"(d2), "+f"(d3)
                 : "r"(a0), "r"(a1), "r"(a2), "r"(a3), "r"(b0), "r"(b1));
}

__device__ __forceinline__ uint32_t f2tf32(float f) {
    uint32_t r;
    asm("cvt.rna.tf32.f32 %0, %1;" : "=r"(r) : "f"(f));
    return r;
}

// Fast exp on the FMA/ALU pipes only (no MUFU). x <= 0 in all our uses.
__device__ __forceinline__ float fexp(float x) {
    x = fmaxf(x, -87.0f);                                   // handles -inf
    const float L2E = 1.4426950408889634f;
    float t = fmaf(x, L2E, 12582912.0f);                    // round-to-nearest magic
    float i = t - 12582912.0f;
    float f = fmaf(x, L2E, -i);                             // f in [-0.5, 0.5]
    float p = 1.5403530393381609e-4f;                       // 2^f Taylor (deg 6)
    p = fmaf(p, f, 1.3333558146428443e-3f);
    p = fmaf(p, f, 9.6181291076284772e-3f);
    p = fmaf(p, f, 5.5504108664821580e-2f);
    p = fmaf(p, f, 2.4022650695910072e-1f);
    p = fmaf(p, f, 6.9314718055994531e-1f);
    p = fmaf(p, f, 1.0f);
    int e = __float_as_int(t) - 0x4B400000;                 // integer part as int
    return __int_as_float(__float_as_int(p) + (e << 23));   // p * 2^e
}

// ---------------------------------------------------------------------------
// Fused dual-attention (tf32 tensor cores) + cls head.
// Grid: (HWM/64, BB). Block: 256 threads = 8 warps.
// CTA handles 64 positions m0..m0+63 as 128 logical Q rows:
//   rows 0..63  : ref queries (feats0),  rows 64..127 : cur queries (feats1).
// Warp w owns rows 16w..16w+15. Q is register-resident (tf32 A-fragments).
// Streams K=V=cur in TN=64 tiles: Kn[n][k] (S-phase B) + Vc[c][n] (PV B).
// Online softmax in c-fragment layout; P round-trips smem per-warp (Pp).
//
// Shared memory (floats), phase-overlaid:
//   Tile phase : Kn[64][132] @0 (8448) | Vc[128][68] @8448 (8704) | Pp[128][68] @17152
//   Q staging  : Qs[128][132] @0 (16896)
//   Epilogue   : Xs[384][68] @0 (26112) ; then Ys[128][66] @0
// Total = 26112 floats = 104448 bytes.
// ---------------------------------------------------------------------------
__global__ void __launch_bounds__(NTHREADS, 1)
fused_attn_tc(const float* __restrict__ reff, const float* __restrict__ curf,
              const float* __restrict__ w2, const float* __restrict__ b2,
              float* __restrict__ out)
{
    extern __shared__ float sm[];
    float* Kn = sm;                 // [64][132]
    float* Vc = sm + 8448;          // [128][68]
    float* Pp = sm + 17152;         // [128][68]
    float* Qs = sm;                 // [128][132] (staging only)

    const int b    = blockIdx.y;
    const int m0   = blockIdx.x * 64;
    const int tid  = threadIdx.x;
    const int warp = tid >> 5;
    const int lane = tid & 31;

    const float* __restrict__ curb = curf + (size_t)b * CC * HWM;
    const float* __restrict__ refb = reff + (size_t)b * CC * HWM;

    const float scale = 0.08838834764831845f;   // 1/sqrt(128)

    // ---- Stage Q (scaled, tf32 bits) into Qs ----
    #pragma unroll
    for (int rep = 0; rep < 8; rep++) {
        int c  = rep * 16 + (tid >> 4);
        int m4 = (tid & 15) * 4;
        float4 vr = *(const float4*)(refb + (size_t)c * HWM + m0 + m4);
        float4 vc = *(const float4*)(curb + (size_t)c * HWM + m0 + m4);
        Qs[(m4 + 0) * 132 + c] = __uint_as_float(f2tf32(vr.x * scale));
        Qs[(m4 + 1) * 132 + c] = __uint_as_float(f2tf32(vr.y * scale));
        Qs[(m4 + 2) * 132 + c] = __uint_as_float(f2tf32(vr.z * scale));
        Qs[(m4 + 3) * 132 + c] = __uint_as_float(f2tf32(vr.w * scale));
        Qs[(64 + m4 + 0) * 132 + c] = __uint_as_float(f2tf32(vc.x * scale));
        Qs[(64 + m4 + 1) * 132 + c] = __uint_as_float(f2tf32(vc.y * scale));
        Qs[(64 + m4 + 2) * 132 + c] = __uint_as_float(f2tf32(vc.z * scale));
        Qs[(64 + m4 + 3) * 132 + c] = __uint_as_float(f2tf32(vc.w * scale));
    }
    __syncthreads();

    // ---- Load Q A-fragments into registers (16 kblocks x 4 regs) ----
    const int g  = lane >> 3;       // ldmatrix tile id
    const int rr = lane & 7;        // row within tile

    uint32_t Qr[16][4];
    {
        uint32_t qbase = smem_u32(Qs + (16 * warp + (g & 1) * 8 + rr) * 132 + (g >> 1) * 4);
        #pragma unroll
        for (int kb = 0; kb < 16; kb++)
            ldsm4(Qr[kb][0], Qr[kb][1], Qr[kb][2], Qr[kb][3], qbase + kb * 8 * 4);
    }

    // Output accumulators: 16 channel-blocks x {c0,c1 (row A), c2,c3 (row A+8)}
    float O[16][4];
    #pragma unroll
    for (int cb = 0; cb < 16; cb++) {
        O[cb][0] = 0.f; O[cb][1] = 0.f; O[cb][2] = 0.f; O[cb][3] = 0.f;
    }
    float mA = -INFINITY, mB = -INFINITY, lA = 0.f, lB = 0.f;

    // ldmatrix base addresses (per-thread)
    uint32_t knb = smem_u32(Kn + rr * 132 + g * 4);                                 // + nb*8*132 + kb2*16
    uint32_t vcb = smem_u32(Vc + ((g >> 1) * 8 + rr) * 68 + (g & 1) * 4);           // + cb2*16*68 + jb*8
    uint32_t ppb = smem_u32(Pp + (16 * warp + (g & 1) * 8 + rr) * 68 + (g >> 1) * 4); // + jb*8

    // ---- Main loop over 64 K/V tiles ----
    for (int nt = 0; nt < HWM / TN; nt++) {
        const int n0 = nt * TN;

        __syncthreads();   // prior tile fully consumed (also Q-ldsm done at nt=0)

        // Load tile: Vc[c][n] (natural) + Kn[n][c] (transpose), tf32 bits
        #pragma unroll
        for (int rep = 0; rep < 8; rep++) {
            int c  = rep * 16 + (tid >> 4);
            int n4 = (tid & 15) * 4;
            float4 v = *(const float4*)(curb + (size_t)c * HWM + n0 + n4);
            uint32_t t0 = f2tf32(v.x), t1 = f2tf32(v.y), t2 = f2tf32(v.z), t3 = f2tf32(v.w);
            *(uint4*)(Vc + c * 68 + n4) = make_uint4(t0, t1, t2, t3);
            Kn[(n4 + 0) * 132 + c] = __uint_as_float(t0);
            Kn[(n4 + 1) * 132 + c] = __uint_as_float(t1);
            Kn[(n4 + 2) * 132 + c] = __uint_as_float(t2);
            Kn[(n4 + 3) * 132 + c] = __uint_as_float(t3);
        }
        __syncthreads();

        // ---- S = Q K^T : 16x64 per warp, 8 nblocks x 16 kblocks ----
        float s[8][4];
        #pragma unroll
        for (int nb = 0; nb < 8; nb++) {
            s[nb][0] = 0.f; s[nb][1] = 0.f; s[nb][2] = 0.f; s[nb][3] = 0.f;
        }
        #pragma unroll
        for (int kb2 = 0; kb2 < 8; kb2++) {
            #pragma unroll
            for (int nb = 0; nb < 8; nb++) {
                uint32_t b0, b1, b2_, b3_;
                ldsm4(b0, b1, b2_, b3_, knb + (nb * 8 * 132 + kb2 * 16) * 4);
                mma_tf32(s[nb][0], s[nb][1], s[nb][2], s[nb][3],
                         Qr[2 * kb2][0], Qr[2 * kb2][1], Qr[2 * kb2][2], Qr[2 * kb2][3],
                         b0, b1);
                mma_tf32(s[nb][0], s[nb][1], s[nb][2], s[nb][3],
                         Qr[2 * kb2 + 1][0], Qr[2 * kb2 + 1][1], Qr[2 * kb2 + 1][2], Qr[2 * kb2 + 1][3],
                         b2_, b3_);
            }
        }

        // ---- Online softmax (rows rA = lane>>2, rB = rA+8) ----
        float rmaxA = s[0][0], rmaxB = s[0][2];
        #pragma unroll
        for (int nb = 0; nb < 8; nb++) {
            rmaxA = fmaxf(rmaxA, fmaxf(s[nb][0], s[nb][1]));
            rmaxB = fmaxf(rmaxB, fmaxf(s[nb][2], s[nb][3]));
        }
        rmaxA = fmaxf(rmaxA, __shfl_xor_sync(0xffffffffu, rmaxA, 1));
        rmaxA = fmaxf(rmaxA, __shfl_xor_sync(0xffffffffu, rmaxA, 2));
        rmaxB = fmaxf(rmaxB, __shfl_xor_sync(0xffffffffu, rmaxB, 1));
        rmaxB = fmaxf(rmaxB, __shfl_xor_sync(0xffffffffu, rmaxB, 2));

        float nmA = fmaxf(mA, rmaxA), nmB = fmaxf(mB, rmaxB);
        float aA = fexp(mA - nmA),   aB = fexp(mB - nmB);
        mA = nmA; mB = nmB;

        float sumA = 0.f, sumB = 0.f;
        #pragma unroll
        for (int nb = 0; nb < 8; nb++) {
            float p0 = fexp(s[nb][0] - nmA);
            float p1 = fexp(s[nb][1] - nmA);
            float p2 = fexp(s[nb][2] - nmB);
            float p3 = fexp(s[nb][3] - nmB);
            s[nb][0] = p0; s[nb][1] = p1; s[nb][2] = p2; s[nb][3] = p3;
            sumA += p0 + p1;
            sumB += p2 + p3;
        }
        sumA += __shfl_xor_sync(0xffffffffu, sumA, 1);
        sumA += __shfl_xor_sync(0xffffffffu, sumA, 2);
        sumB += __shfl_xor_sync(0xffffffffu, sumB, 1);
        sumB += __shfl_xor_sync(0xffffffffu, sumB, 2);
        lA = lA * aA + sumA;
        lB = lB * aB + sumB;

        #pragma unroll
        for (int cb = 0; cb < 16; cb++) {
            O[cb][0] *= aA; O[cb][1] *= aA;
            O[cb][2] *= aB; O[cb][3] *= aB;
        }

        // ---- Stage P (tf32) to per-warp smem region ----
        {
            int rowA = 16 * warp + (lane >> 2);
            int col  = 2 * (lane & 3);
            #pragma unroll
            for (int nb = 0; nb < 8; nb++) {
                *(uint2*)(Pp + rowA * 68 + nb * 8 + col) =
                    make_uint2(f2tf32(s[nb][0]), f2tf32(s[nb][1]));
                *(uint2*)(Pp + (rowA + 8) * 68 + nb * 8 + col) =
                    make_uint2(f2tf32(s[nb][2]), f2tf32(s[nb][3]));
            }
        }
        __syncwarp();

        // ---- O += P V : 8 jblocks x 16 cblocks per warp ----
        #pragma unroll
        for (int jb = 0; jb < 8; jb++) {
            uint32_t a0, a1, a2, a3;
            ldsm4(a0, a1, a2, a3, ppb + jb * 8 * 4);
            #pragma unroll
            for (int cb2 = 0; cb2 < 8; cb2++) {
                uint32_t b0, b1, b2_, b3_;
                ldsm4(b0, b1, b2_, b3_, vcb + (cb2 * 16 * 68 + jb * 8) * 4);
                mma_tf32(O[2 * cb2][0], O[2 * cb2][1], O[2 * cb2][2], O[2 * cb2][3],
                         a0, a1, a2, a3, b0, b1);
                mma_tf32(O[2 * cb2 + 1][0], O[2 * cb2 + 1][1], O[2 * cb2 + 1][2], O[2 * cb2 + 1][3],
                         a0, a1, a2, a3, b2_, b3_);
            }
        }
    }
    __syncthreads();   // attention done; smem free for epilogue

    // ---- Build X = [feats0; feats1; cur] : Xs[384][68] over 64 m ----
    float* Xs = sm;
    {
        float rlA = 1.0f / lA, rlB = 1.0f / lB;
        int rA = 16 * warp + (lane >> 2);
        int rB = rA + 8;
        int aSelA = rA >> 6, mmA = rA & 63;
        int aSelB = rB >> 6, mmB = rB & 63;
        #pragma unroll
        for (int cb = 0; cb < 16; cb++) {
            int c = cb * 8 + 2 * (lane & 3);
            Xs[(aSelA * CC + c    ) * 68 + mmA] = O[cb][0] * rlA;
            Xs[(aSelA * CC + c + 1) * 68 + mmA] = O[cb][1] * rlA;
            Xs[(aSelB * CC + c    ) * 68 + mmB] = O[cb][2] * rlB;
            Xs[(aSelB * CC + c + 1) * 68 + mmB] = O[cb][3] * rlB;
        }
    }
    for (int i = tid; i < CC * 64; i += NTHREADS) {
        int c  = i >> 6;
        int mm = i & 63;
        Xs[(2 * CC + c) * 68 + mm] = curb[(size_t)c * HWM + m0 + mm];
    }
    __syncthreads();

    // ---- cls head: y[o][m] = sum_c At[c][o] X[c][m] + dv[o]; leaky; *w2[o] ----
    float y[32];
    float w2o;
    {
        int o    = tid & 127;
        int half = tid >> 7;
        float dv = g_dv[o];
        #pragma unroll
        for (int q = 0; q < 32; q++) y[q] = dv;

        const float* xb = Xs + half * 32;
        #pragma unroll 2
        for (int c = 0; c < 3 * CC; c++) {
            float a = g_At[c * CC + o];
            const float4* xp = (const float4*)(xb + c * 68);
            #pragma unroll
            for (int v = 0; v < 8; v++) {
                float4 x = xp[v];
                y[4 * v + 0] += a * x.x;
                y[4 * v + 1] += a * x.y;
                y[4 * v + 2] += a * x.z;
                y[4 * v + 3] += a * x.w;
            }
        }
        w2o = w2[o];
    }
    __syncthreads();   // Xs dead

    float* Ys = sm;    // [128][66]
    {
        int o    = tid & 127;
        int half = tid >> 7;
        #pragma unroll
        for (int q = 0; q < 32; q++) {
            float v = y[q];
            v = (v > 0.0f) ? v : 0.01f * v;
            Ys[o * 66 + half * 32 + q] = w2o * v;
        }
    }
    __syncthreads();

    if (tid < 64) {
        float ssum = b2[0];
        #pragma unroll 4
        for (int o = 0; o < CC; o++) ssum += Ys[o * 66 + tid];
        out[(size_t)b * HWM + m0 + tid] = ssum;
    }
}

extern "C" void kernel_launch(void* const* d_in, const int* in_sizes, int n_in,
                              void* d_out, int out_size)
{
    const float* ref_feat = (const float*)d_in[0];
    const float* cur_feat = (const float*)d_in[1];
    const float* w1       = (const float*)d_in[2];
    const float* b1       = (const float*)d_in[3];
    const float* gamma    = (const float*)d_in[4];
    const float* beta     = (const float*)d_in[5];
    const float* rmean    = (const float*)d_in[6];
    const float* rvar     = (const float*)d_in[7];
    const float* w2       = (const float*)d_in[8];
    const float* b2       = (const float*)d_in[9];
    float* out            = (float*)d_out;

    prep_kernel<<<(3 * CC * CC + 255) / 256, 256>>>(w1, b1, gamma, beta, rmean, rvar);

    const int smem_bytes = 26112 * 4;  // 104448
    cudaFuncSetAttribute(fused_attn_tc,
                         cudaFuncAttributeMaxDynamicSharedMemorySize, smem_bytes);

    dim3 grid(HWM / 64, BB);
    fused_attn_tc<<<grid, NTHREADS, smem_bytes>>>(ref_feat, cur_feat, w2, b2, out);
}

// round 7
// speedup vs baseline: 2.7736x; 1.0002x over previous
#include <cuda_runtime.h>
#include <math.h>
#include <stdint.h>

#define BB 8
#define CC 128
#define HWM 4096          // H*W
#define TN 64             // K/V tile width
#define NTHREADS 256

// Folded classifier-head weights (BN folded into w1).
__device__ float g_At[3 * CC * CC];   // At[c][o] = w1[o][c] * inv[o]
__device__ float g_dv[CC];

__global__ void prep_kernel(const float* __restrict__ w1, const float* __restrict__ b1,
                            const float* __restrict__ gamma, const float* __restrict__ beta,
                            const float* __restrict__ rmean, const float* __restrict__ rvar)
{
    int i = blockIdx.x * blockDim.x + threadIdx.x;
    if (i < 3 * CC * CC) {
        int c = i / CC;
        int o = i % CC;
        float inv = gamma[o] * rsqrtf(rvar[o] + 1e-5f);
        g_At[c * CC + o] = w1[o * (3 * CC) + c] * inv;
    }
    if (i < CC) {
        float inv = gamma[i] * rsqrtf(rvar[i] + 1e-5f);
        g_dv[i] = b1[i] * inv + beta[i] - rmean[i] * inv;
    }
}

// ---------- PTX helpers ----------
__device__ __forceinline__ uint32_t smem_u32(const void* p) {
    return (uint32_t)__cvta_generic_to_shared(p);
}

__device__ __forceinline__ void ldsm4(uint32_t& r0, uint32_t& r1, uint32_t& r2, uint32_t& r3,
                                      uint32_t addr) {
    asm volatile("ldmatrix.sync.aligned.m8n8.x4.shared.b16 {%0,%1,%2,%3}, [%4];"
                 : "=r"(r0), "=r"(r1), "=r"(r2), "=r"(r3) : "r"(addr));
}

__device__ __forceinline__ void mma_tf32(float& d0, float& d1, float& d2, float& d3,
                                         uint32_t a0, uint32_t a1, uint32_t a2, uint32_t a3,
                                         uint32_t b0, uint32_t b1) {
    asm volatile("mma.sync.aligned.m16n8k8.row.col.f32.tf32.tf32.f32 "
                 "{%0,%1,%2,%3}, {%4,%5,%6,%7}, {%8,%9}, {%0,%1,%2,%3};"
                 : "+f"(d0), "+f"(d1), "+f"(d2), "+f"(d3)
                 : "r"(a0), "r"(a1), "r"(a2), "r"(a3), "r"(b0), "r"(b1));
}

__device__ __forceinline__ uint32_t f2tf32(float f) {
    uint32_t r;
    asm("cvt.rna.tf32.f32 %0, %1;" : "=r"(r) : "f"(f));
    return r;
}

// Fast exp on the FMA/ALU pipes only (no MUFU). x <= 0 in all our uses.
__device__ __forceinline__ float fexp(float x) {
    x = fmaxf(x, -87.0f);                                   // handles -inf
    const float L2E = 1.4426950408889634f;
    float t = fmaf(x, L2E, 12582912.0f);                    // round-to-nearest magic
    float i = t - 12582912.0f;
    float f = fmaf(x, L2E, -i);                             // f in [-0.5, 0.5]
    float p = 1.5403530393381609e-4f;                       // 2^f Taylor (deg 6)
    p = fmaf(p, f, 1.3333558146428443e-3f);
    p = fmaf(p, f, 9.6181291076284772e-3f);
    p = fmaf(p, f, 5.5504108664821580e-2f);
    p = fmaf(p, f, 2.4022650695910072e-1f);
    p = fmaf(p, f, 6.9314718055994531e-1f);
    p = fmaf(p, f, 1.0f);
    int e = __float_as_int(t) - 0x4B400000;                 // integer part as int
    return __int_as_float(__float_as_int(p) + (e << 23));   // p * 2^e
}

// ---------------------------------------------------------------------------
// Fused dual-attention (tf32 tensor cores) + cls head.
// Grid: (HWM/64, BB). Block: 256 threads = 8 warps.
// CTA handles 64 positions m0..m0+63 as 128 logical Q rows:
//   rows 0..63  : ref queries (feats0),  rows 64..127 : cur queries (feats1).
// Warp w owns rows 16w..16w+15. Q is register-resident (tf32 A-fragments).
// Streams K=V=cur in TN=64 tiles: Kn[n][k] (S-phase B) + Vc[c][n] (PV B).
// Online softmax in c-fragment layout; P round-trips smem per-warp (Pp).
//
// Shared memory (floats), phase-overlaid:
//   Tile phase : Kn[64][132] @0 (8448) | Vc[128][68] @8448 (8704) | Pp[128][68] @17152
//   Q staging  : Qs[128][132] @0 (16896)
//   Epilogue   : Xs[384][68] @0 (26112) ; then Ys[128][66] @0
// Total = 26112 floats = 104448 bytes.
// ---------------------------------------------------------------------------
__global__ void __launch_bounds__(NTHREADS, 1)
fused_attn_tc(const float* __restrict__ reff, const float* __restrict__ curf,
              const float* __restrict__ w2, const float* __restrict__ b2,
              float* __restrict__ out)
{
    extern __shared__ float sm[];
    float* Kn = sm;                 // [64][132]
    float* Vc = sm + 8448;          // [128][68]
    float* Pp = sm + 17152;         // [128][68]
    float* Qs = sm;                 // [128][132] (staging only)

    const int b    = blockIdx.y;
    const int m0   = blockIdx.x * 64;
    const int tid  = threadIdx.x;
    const int warp = tid >> 5;
    const int lane = tid & 31;

    const float* __restrict__ curb = curf + (size_t)b * CC * HWM;
    const float* __restrict__ refb = reff + (size_t)b * CC * HWM;

    const float scale = 0.08838834764831845f;   // 1/sqrt(128)

    // ---- Stage Q (scaled, tf32 bits) into Qs ----
    #pragma unroll
    for (int rep = 0; rep < 8; rep++) {
        int c  = rep * 16 + (tid >> 4);
        int m4 = (tid & 15) * 4;
        float4 vr = *(const float4*)(refb + (size_t)c * HWM + m0 + m4);
        float4 vc = *(const float4*)(curb + (size_t)c * HWM + m0 + m4);
        Qs[(m4 + 0) * 132 + c] = __uint_as_float(f2tf32(vr.x * scale));
        Qs[(m4 + 1) * 132 + c] = __uint_as_float(f2tf32(vr.y * scale));
        Qs[(m4 + 2) * 132 + c] = __uint_as_float(f2tf32(vr.z * scale));
        Qs[(m4 + 3) * 132 + c] = __uint_as_float(f2tf32(vr.w * scale));
        Qs[(64 + m4 + 0) * 132 + c] = __uint_as_float(f2tf32(vc.x * scale));
        Qs[(64 + m4 + 1) * 132 + c] = __uint_as_float(f2tf32(vc.y * scale));
        Qs[(64 + m4 + 2) * 132 + c] = __uint_as_float(f2tf32(vc.z * scale));
        Qs[(64 + m4 + 3) * 132 + c] = __uint_as_float(f2tf32(vc.w * scale));
    }
    __syncthreads();

    // ---- Load Q A-fragments into registers (16 kblocks x 4 regs) ----
    const int g  = lane >> 3;       // ldmatrix tile id
    const int rr = lane & 7;        // row within tile

    uint32_t Qr[16][4];
    {
        uint32_t qbase = smem_u32(Qs + (16 * warp + (g & 1) * 8 + rr) * 132 + (g >> 1) * 4);
        #pragma unroll
        for (int kb = 0; kb < 16; kb++)
            ldsm4(Qr[kb][0], Qr[kb][1], Qr[kb][2], Qr[kb][3], qbase + kb * 8 * 4);
    }

    // Output accumulators: 16 channel-blocks x {c0,c1 (row A), c2,c3 (row A+8)}
    float O[16][4];
    #pragma unroll
    for (int cb = 0; cb < 16; cb++) {
        O[cb][0] = 0.f; O[cb][1] = 0.f; O[cb][2] = 0.f; O[cb][3] = 0.f;
    }
    float mA = -INFINITY, mB = -INFINITY, lA = 0.f, lB = 0.f;

    // ldmatrix base addresses (per-thread)
    uint32_t knb = smem_u32(Kn + rr * 132 + g * 4);                                 // + nb*8*132 + kb2*16
    uint32_t vcb = smem_u32(Vc + ((g >> 1) * 8 + rr) * 68 + (g & 1) * 4);           // + cb2*16*68 + jb*8
    uint32_t ppb = smem_u32(Pp + (16 * warp + (g & 1) * 8 + rr) * 68 + (g >> 1) * 4); // + jb*8

    // ---- Main loop over 64 K/V tiles ----
    for (int nt = 0; nt < HWM / TN; nt++) {
        const int n0 = nt * TN;

        __syncthreads();   // prior tile fully consumed (also Q-ldsm done at nt=0)

        // Load tile: Vc[c][n] (natural) + Kn[n][c] (transpose), tf32 bits
        #pragma unroll
        for (int rep = 0; rep < 8; rep++) {
            int c  = rep * 16 + (tid >> 4);
            int n4 = (tid & 15) * 4;
            float4 v = *(const float4*)(curb + (size_t)c * HWM + n0 + n4);
            uint32_t t0 = f2tf32(v.x), t1 = f2tf32(v.y), t2 = f2tf32(v.z), t3 = f2tf32(v.w);
            *(uint4*)(Vc + c * 68 + n4) = make_uint4(t0, t1, t2, t3);
            Kn[(n4 + 0) * 132 + c] = __uint_as_float(t0);
            Kn[(n4 + 1) * 132 + c] = __uint_as_float(t1);
            Kn[(n4 + 2) * 132 + c] = __uint_as_float(t2);
            Kn[(n4 + 3) * 132 + c] = __uint_as_float(t3);
        }
        __syncthreads();

        // ---- S = Q K^T : 16x64 per warp, 8 nblocks x 16 kblocks ----
        float s[8][4];
        #pragma unroll
        for (int nb = 0; nb < 8; nb++) {
            s[nb][0] = 0.f; s[nb][1] = 0.f; s[nb][2] = 0.f; s[nb][3] = 0.f;
        }
        #pragma unroll
        for (int kb2 = 0; kb2 < 8; kb2++) {
            #pragma unroll
            for (int nb = 0; nb < 8; nb++) {
                uint32_t b0, b1, b2_, b3_;
                ldsm4(b0, b1, b2_, b3_, knb + (nb * 8 * 132 + kb2 * 16) * 4);
                mma_tf32(s[nb][0], s[nb][1], s[nb][2], s[nb][3],
                         Qr[2 * kb2][0], Qr[2 * kb2][1], Qr[2 * kb2][2], Qr[2 * kb2][3],
                         b0, b1);
                mma_tf32(s[nb][0], s[nb][1], s[nb][2], s[nb][3],
                         Qr[2 * kb2 + 1][0], Qr[2 * kb2 + 1][1], Qr[2 * kb2 + 1][2], Qr[2 * kb2 + 1][3],
                         b2_, b3_);
            }
        }

        // ---- Online softmax (rows rA = lane>>2, rB = rA+8) ----
        float rmaxA = s[0][0], rmaxB = s[0][2];
        #pragma unroll
        for (int nb = 0; nb < 8; nb++) {
            rmaxA = fmaxf(rmaxA, fmaxf(s[nb][0], s[nb][1]));
            rmaxB = fmaxf(rmaxB, fmaxf(s[nb][2], s[nb][3]));
        }
        rmaxA = fmaxf(rmaxA, __shfl_xor_sync(0xffffffffu, rmaxA, 1));
        rmaxA = fmaxf(rmaxA, __shfl_xor_sync(0xffffffffu, rmaxA, 2));
        rmaxB = fmaxf(rmaxB, __shfl_xor_sync(0xffffffffu, rmaxB, 1));
        rmaxB = fmaxf(rmaxB, __shfl_xor_sync(0xffffffffu, rmaxB, 2));

        float nmA = fmaxf(mA, rmaxA), nmB = fmaxf(mB, rmaxB);
        float aA = fexp(mA - nmA),   aB = fexp(mB - nmB);
        mA = nmA; mB = nmB;

        float sumA = 0.f, sumB = 0.f;
        #pragma unroll
        for (int nb = 0; nb < 8; nb++) {
            float p0 = fexp(s[nb][0] - nmA);
            float p1 = fexp(s[nb][1] - nmA);
            float p2 = fexp(s[nb][2] - nmB);
            float p3 = fexp(s[nb][3] - nmB);
            s[nb][0] = p0; s[nb][1] = p1; s[nb][2] = p2; s[nb][3] = p3;
            sumA += p0 + p1;
            sumB += p2 + p3;
        }
        sumA += __shfl_xor_sync(0xffffffffu, sumA, 1);
        sumA += __shfl_xor_sync(0xffffffffu, sumA, 2);
        sumB += __shfl_xor_sync(0xffffffffu, sumB, 1);
        sumB += __shfl_xor_sync(0xffffffffu, sumB, 2);
        lA = lA * aA + sumA;
        lB = lB * aB + sumB;

        #pragma unroll
        for (int cb = 0; cb < 16; cb++) {
            O[cb][0] *= aA; O[cb][1] *= aA;
            O[cb][2] *= aB; O[cb][3] *= aB;
        }

        // ---- Stage P (tf32) to per-warp smem region ----
        {
            int rowA = 16 * warp + (lane >> 2);
            int col  = 2 * (lane & 3);
            #pragma unroll
            for (int nb = 0; nb < 8; nb++) {
                *(uint2*)(Pp + rowA * 68 + nb * 8 + col) =
                    make_uint2(f2tf32(s[nb][0]), f2tf32(s[nb][1]));
                *(uint2*)(Pp + (rowA + 8) * 68 + nb * 8 + col) =
                    make_uint2(f2tf32(s[nb][2]), f2tf32(s[nb][3]));
            }
        }
        __syncwarp();

        // ---- O += P V : 8 jblocks x 16 cblocks per warp ----
        #pragma unroll
        for (int jb = 0; jb < 8; jb++) {
            uint32_t a0, a1, a2, a3;
            ldsm4(a0, a1, a2, a3, ppb + jb * 8 * 4);
            #pragma unroll
            for (int cb2 = 0; cb2 < 8; cb2++) {
                uint32_t b0, b1, b2_, b3_;
                ldsm4(b0, b1, b2_, b3_, vcb + (cb2 * 16 * 68 + jb * 8) * 4);
                mma_tf32(O[2 * cb2][0], O[2 * cb2][1], O[2 * cb2][2], O[2 * cb2][3],
                         a0, a1, a2, a3, b0, b1);
                mma_tf32(O[2 * cb2 + 1][0], O[2 * cb2 + 1][1], O[2 * cb2 + 1][2], O[2 * cb2 + 1][3],
                         a0, a1, a2, a3, b2_, b3_);
            }
        }
    }
    __syncthreads();   // attention done; smem free for epilogue

    // ---- Build X = [feats0; feats1; cur] : Xs[384][68] over 64 m ----
    float* Xs = sm;
    {
        float rlA = 1.0f / lA, rlB = 1.0f / lB;
        int rA = 16 * warp + (lane >> 2);
        int rB = rA + 8;
        int aSelA = rA >> 6, mmA = rA & 63;
        int aSelB = rB >> 6, mmB = rB & 63;
        #pragma unroll
        for (int cb = 0; cb < 16; cb++) {
            int c = cb * 8 + 2 * (lane & 3);
            Xs[(aSelA * CC + c    ) * 68 + mmA] = O[cb][0] * rlA;
            Xs[(aSelA * CC + c + 1) * 68 + mmA] = O[cb][1] * rlA;
            Xs[(aSelB * CC + c    ) * 68 + mmB] = O[cb][2] * rlB;
            Xs[(aSelB * CC + c + 1) * 68 + mmB] = O[cb][3] * rlB;
        }
    }
    for (int i = tid; i < CC * 64; i += NTHREADS) {
        int c  = i >> 6;
        int mm = i & 63;
        Xs[(2 * CC + c) * 68 + mm] = curb[(size_t)c * HWM + m0 + mm];
    }
    __syncthreads();

    // ---- cls head: y[o][m] = sum_c At[c][o] X[c][m] + dv[o]; leaky; *w2[o] ----
    float y[32];
    float w2o;
    {
        int o    = tid & 127;
        int half = tid >> 7;
        float dv = g_dv[o];
        #pragma unroll
        for (int q = 0; q < 32; q++) y[q] = dv;

        const float* xb = Xs + half * 32;
        #pragma unroll 2
        for (int c = 0; c < 3 * CC; c++) {
            float a = g_At[c * CC + o];
            const float4* xp = (const float4*)(xb + c * 68);
            #pragma unroll
            for (int v = 0; v < 8; v++) {
                float4 x = xp[v];
                y[4 * v + 0] += a * x.x;
                y[4 * v + 1] += a * x.y;
                y[4 * v + 2] += a * x.z;
                y[4 * v + 3] += a * x.w;
            }
        }
        w2o = w2[o];
    }
    __syncthreads();   // Xs dead

    float* Ys = sm;    // [128][66]
    {
        int o    = tid & 127;
        int half = tid >> 7;
        #pragma unroll
        for (int q = 0; q < 32; q++) {
            float v = y[q];
            v = (v > 0.0f) ? v : 0.01f * v;
            Ys[o * 66 + half * 32 + q] = w2o * v;
        }
    }
    __syncthreads();

    if (tid < 64) {
        float ssum = b2[0];
        #pragma unroll 4
        for (int o = 0; o < CC; o++) ssum += Ys[o * 66 + tid];
        out[(size_t)b * HWM + m0 + tid] = ssum;
    }
}

extern "C" void kernel_launch(void* const* d_in, const int* in_sizes, int n_in,
                              void* d_out, int out_size)
{
    const float* ref_feat = (const float*)d_in[0];
    const float* cur_feat = (const float*)d_in[1];
    const float* w1       = (const float*)d_in[2];
    const float* b1       = (const float*)d_in[3];
    const float* gamma    = (const float*)d_in[4];
    const float* beta     = (const float*)d_in[5];
    const float* rmean    = (const float*)d_in[6];
    const float* rvar     = (const float*)d_in[7];
    const float* w2       = (const float*)d_in[8];
    const float* b2       = (const float*)d_in[9];
    float* out            = (float*)d_out;

    prep_kernel<<<(3 * CC * CC + 255) / 256, 256>>>(w1, b1, gamma, beta, rmean, rvar);

    const int smem_bytes = 26112 * 4;  // 104448
    cudaFuncSetAttribute(fused_attn_tc,
                         cudaFuncAttributeMaxDynamicSharedMemorySize, smem_bytes);

    dim3 grid(HWM / 64, BB);
    fused_attn_tc<<<grid, NTHREADS, smem_bytes>>>(ref_feat, cur_feat, w2, b2, out);
}